// round 2
// baseline (speedup 1.0000x reference)
#include <cuda_runtime.h>
#include <math.h>

// ---------------- problem constants (fixed by dataset) ----------------
#define B_     8
#define T2_    27
#define T3_    9
#define P_     17
#define C_     128
#define BT2_   216            // B*T2
#define LQ_    153            // T3*P
#define LV_    4080
#define NH_    8
#define NL_    4
#define NP_    4
#define DH_    16
#define NROWS_ (BT2_*LQ_)     // 33048 query rows
#define MVAL_  (BT2_*LV_)     // 881280 value rows
#define NEWQ_SIZE_ ((size_t)NROWS_*C_)   // 4230144
#define NOFF_  256            // NH*NL*NP*2
#define NCAT_  384            // 256 off + 128 attn

// ---------------- scratch (static __device__, no allocs) ----------------
__device__ float g_offatt[(size_t)NROWS_ * NCAT_];   // off cols [0,256), attn logits [256,384)
__device__ float g_att[(size_t)NROWS_ * C_];         // softmaxed attn weights
__device__ float g_samp[(size_t)NROWS_ * C_];        // gathered output before W_out
__device__ float g_wcat[NCAT_ * C_];
__device__ float g_bcat[NCAT_];

// ---------------- f32x2 packed-FMA helpers ----------------
__device__ __forceinline__ unsigned long long pack2(float x, float y) {
    unsigned long long r;
    asm("mov.b64 %0, {%1, %2};" : "=l"(r) : "f"(x), "f"(y));
    return r;
}
__device__ __forceinline__ unsigned long long dup2(float x) {
    unsigned long long r;
    asm("mov.b64 %0, {%1, %1};" : "=l"(r) : "f"(x));
    return r;
}
__device__ __forceinline__ void ffma2(unsigned long long& d, unsigned long long a, unsigned long long b) {
    asm("fma.rn.f32x2 %0, %1, %2, %0;" : "+l"(d) : "l"(a), "l"(b));
}
__device__ __forceinline__ float2 unpack2(unsigned long long v) {
    float2 f;
    asm("mov.b64 {%0, %1}, %2;" : "=f"(f.x), "=f"(f.y) : "l"(v));
    return f;
}

// ---------------- generic GEMM: Out[m,n] = sum_k A[m,k]*W[n,k] + bias[n] ----------------
// K = 128 fixed. BM = BN = 128 tile, 256 threads (16x16), 8x8 micro-tile,
// f32x2 packed accumulators (pairs along n).
#define KC_ 32
__global__ __launch_bounds__(256) void gemm128_abt(
    const float* __restrict__ A, const float* __restrict__ W,
    const float* __restrict__ bias, float* __restrict__ Out,
    int M, int N)
{
    __shared__ float As[KC_][132];   // transposed: As[k][m], +4 pad for store conflicts
    __shared__ float Bs[KC_][132];   // transposed: Bs[k][n]

    const int bm = blockIdx.x * 128;
    const int bn = blockIdx.y * 128;
    const int tid = threadIdx.x;
    const int tx = tid & 15;         // n direction
    const int ty = tid >> 4;         // m direction

    unsigned long long acc[8][4];
#pragma unroll
    for (int i = 0; i < 8; i++)
#pragma unroll
        for (int j = 0; j < 4; j++) acc[i][j] = 0ull;

    for (int k0 = 0; k0 < 128; k0 += KC_) {
        // load A chunk (128 rows x KC_ k), transposed into As
#pragma unroll
        for (int it = 0; it < 4; it++) {
            int q   = it * 256 + tid;         // 0..1023 float4 slots
            int row = q >> 3;                 // 0..127
            int kq  = q & 7;                  // float4 within chunk
            int grow = bm + row;
            float4 v = make_float4(0.f, 0.f, 0.f, 0.f);
            if (grow < M)
                v = *(const float4*)(A + (size_t)grow * 128 + k0 + kq * 4);
            As[kq * 4 + 0][row] = v.x;
            As[kq * 4 + 1][row] = v.y;
            As[kq * 4 + 2][row] = v.z;
            As[kq * 4 + 3][row] = v.w;
        }
        // load W chunk (128 n-rows x KC_ k), transposed into Bs (N is multiple of 128)
#pragma unroll
        for (int it = 0; it < 4; it++) {
            int q   = it * 256 + tid;
            int row = q >> 3;
            int kq  = q & 7;
            float4 v = *(const float4*)(W + (size_t)(bn + row) * 128 + k0 + kq * 4);
            Bs[kq * 4 + 0][row] = v.x;
            Bs[kq * 4 + 1][row] = v.y;
            Bs[kq * 4 + 2][row] = v.z;
            Bs[kq * 4 + 3][row] = v.w;
        }
        __syncthreads();

#pragma unroll
        for (int k = 0; k < KC_; k++) {
            float4 a0 = *(const float4*)&As[k][ty * 8];
            float4 a1 = *(const float4*)&As[k][ty * 8 + 4];
            float4 b0 = *(const float4*)&Bs[k][tx * 8];
            float4 b1 = *(const float4*)&Bs[k][tx * 8 + 4];
            unsigned long long bp0 = pack2(b0.x, b0.y);
            unsigned long long bp1 = pack2(b0.z, b0.w);
            unsigned long long bp2 = pack2(b1.x, b1.y);
            unsigned long long bp3 = pack2(b1.z, b1.w);
            float av[8] = {a0.x, a0.y, a0.z, a0.w, a1.x, a1.y, a1.z, a1.w};
#pragma unroll
            for (int i = 0; i < 8; i++) {
                unsigned long long ad = dup2(av[i]);
                ffma2(acc[i][0], ad, bp0);
                ffma2(acc[i][1], ad, bp1);
                ffma2(acc[i][2], ad, bp2);
                ffma2(acc[i][3], ad, bp3);
            }
        }
        __syncthreads();
    }

    // epilogue: bias + store
    const int gcol = bn + tx * 8;
#pragma unroll
    for (int i = 0; i < 8; i++) {
        int grow = bm + ty * 8 + i;
        if (grow >= M) continue;
        float o[8];
#pragma unroll
        for (int j = 0; j < 4; j++) {
            float2 f = unpack2(acc[i][j]);
            o[j * 2 + 0] = f.x;
            o[j * 2 + 1] = f.y;
        }
#pragma unroll
        for (int j = 0; j < 8; j++) o[j] += bias[gcol + j];
        float* dst = Out + (size_t)grow * N + gcol;
        *(float4*)(dst + 0) = make_float4(o[0], o[1], o[2], o[3]);
        *(float4*)(dst + 4) = make_float4(o[4], o[5], o[6], o[7]);
    }
}

// ---------------- concat W_off|W_attn and biases ----------------
__global__ void concat_weights(const float* __restrict__ Woff, const float* __restrict__ boff,
                               const float* __restrict__ Wattn, const float* __restrict__ battn)
{
    int i = blockIdx.x * 256 + threadIdx.x;
    if (i < NOFF_ * C_)                       g_wcat[i] = Woff[i];
    else if (i < NCAT_ * C_)                  g_wcat[i] = Wattn[i - NOFF_ * C_];
    if (i < NOFF_)                            g_bcat[i] = boff[i];
    else if (i < NCAT_)                       g_bcat[i] = battn[i - NOFF_];
}

// ---------------- softmax over 16 logits per (row, head) ----------------
__global__ __launch_bounds__(256) void softmax16_kernel()
{
    int g = blockIdx.x * 256 + threadIdx.x;
    if (g >= NROWS_ * NH_) return;
    int r = g >> 3, h = g & 7;
    const float* src = g_offatt + (size_t)r * NCAT_ + NOFF_ + h * 16;
    float v[16];
    float mx = -INFINITY;
#pragma unroll
    for (int i = 0; i < 16; i++) { v[i] = src[i]; mx = fmaxf(mx, v[i]); }
    float s = 0.f;
#pragma unroll
    for (int i = 0; i < 16; i++) { v[i] = expf(v[i] - mx); s += v[i]; }
    float inv = 1.f / s;
    float* dst = g_att + (size_t)r * C_ + h * 16;
#pragma unroll
    for (int i = 0; i < 16; i++) dst[i] = v[i] * inv;
}

// ---------------- deformable bilinear gather ----------------
// one warp per (row, head); 2 threads per (level, point) sample, 8 channels each.
__global__ __launch_bounds__(128) void gather_kernel(
    const float* __restrict__ newv,      // (BT2, LV, 128) = vproj
    const float* __restrict__ refp)      // (BT2, LQ, 4, 2)
{
    int g = blockIdx.x * 4 + (threadIdx.x >> 5);
    int r = g >> 3;
    int h = g & 7;
    int lane = threadIdx.x & 31;
    int s = lane >> 1;           // sample 0..15
    int half = lane & 1;         // channel half
    int l = s >> 2, p = s & 3;
    int b = r / LQ_;

    const int W = 48 >> l;
    const int H = 64 >> l;
    const int start = 4096 - (4096 >> (2 * l));

    int sidx = (h * 4 + l) * 4 + p;
    const float* orow = g_offatt + (size_t)r * NCAT_;
    float offx = orow[sidx * 2 + 0];
    float offy = orow[sidx * 2 + 1];
    float aw = g_att[(size_t)r * C_ + h * 16 + l * 4 + p];
    const float* rp = refp + ((size_t)r * 4 + l) * 2;
    float locx = rp[0] + offx / (float)W;
    float locy = rp[1] + offy / (float)H;
    float px = locx * (float)W - 0.5f;
    float py = locy * (float)H - 0.5f;
    float x0f = floorf(px), y0f = floorf(py);
    float fx = px - x0f, fy = py - y0f;
    int x0 = (int)x0f, y0 = (int)y0f;

    float cw00 = (1.f - fx) * (1.f - fy) * aw;
    float cw10 = fx * (1.f - fy) * aw;
    float cw01 = (1.f - fx) * fy * aw;
    float cw11 = fx * fy * aw;

    const float* base = newv + ((size_t)b * LV_ + start) * C_ + h * DH_ + half * 8;

    float acc[8] = {0.f, 0.f, 0.f, 0.f, 0.f, 0.f, 0.f, 0.f};

    auto corner = [&](int xi, int yi, float cw) {
        if ((unsigned)xi < (unsigned)W && (unsigned)yi < (unsigned)H) {
            const float4* vp = (const float4*)(base + ((size_t)yi * W + xi) * C_);
            float4 v0 = vp[0], v1 = vp[1];
            acc[0] += cw * v0.x; acc[1] += cw * v0.y;
            acc[2] += cw * v0.z; acc[3] += cw * v0.w;
            acc[4] += cw * v1.x; acc[5] += cw * v1.y;
            acc[6] += cw * v1.z; acc[7] += cw * v1.w;
        }
    };
    corner(x0,     y0,     cw00);
    corner(x0 + 1, y0,     cw10);
    corner(x0,     y0 + 1, cw01);
    corner(x0 + 1, y0 + 1, cw11);

    // reduce over the 16 samples (lane bits 1..4), keep channel-half (bit 0)
#pragma unroll
    for (int m = 2; m <= 16; m <<= 1) {
#pragma unroll
        for (int i = 0; i < 8; i++)
            acc[i] += __shfl_xor_sync(0xffffffffu, acc[i], m);
    }

    if (s == 0) {
        float* dst = g_samp + (size_t)r * C_ + h * DH_ + half * 8;
        *(float4*)(dst + 0) = make_float4(acc[0], acc[1], acc[2], acc[3]);
        *(float4*)(dst + 4) = make_float4(acc[4], acc[5], acc[6], acc[7]);
    }
}

// ---------------- launch ----------------
extern "C" void kernel_launch(void* const* d_in, const int* in_sizes, int n_in,
                              void* d_out, int out_size)
{
    const float* query  = (const float*)d_in[0];   // (8,243,17,128) == (33048,128)
    const float* refp   = (const float*)d_in[1];   // (216,153,4,2)
    const float* value  = (const float*)d_in[2];   // (216,4080,128)
    // d_in[3] indices, d_in[4] input_shapes: constants, hardcoded
    const float* W_off  = (const float*)d_in[5];
    const float* b_off  = (const float*)d_in[6];
    const float* W_attn = (const float*)d_in[7];
    const float* b_attn = (const float*)d_in[8];
    const float* W_val  = (const float*)d_in[9];
    const float* b_val  = (const float*)d_in[10];
    const float* W_out  = (const float*)d_in[11];
    const float* b_out  = (const float*)d_in[12];

    float* NEWQ = (float*)d_out;
    float* NEWV = NEWQ + NEWQ_SIZE_;

    float *p_offatt, *p_att, *p_samp, *p_wcat, *p_bcat;
    cudaGetSymbolAddress((void**)&p_offatt, g_offatt);
    cudaGetSymbolAddress((void**)&p_att,    g_att);
    cudaGetSymbolAddress((void**)&p_samp,   g_samp);
    cudaGetSymbolAddress((void**)&p_wcat,   g_wcat);
    cudaGetSymbolAddress((void**)&p_bcat,   g_bcat);

    // 1) concat offset/attn weights
    concat_weights<<<(NCAT_ * C_ + 255) / 256, 256>>>(W_off, b_off, W_attn, b_attn);

    // 2) value projection -> new_value (the big GEMM)
    gemm128_abt<<<dim3(MVAL_ / 128, 1), 256>>>(value, W_val, b_val, NEWV, MVAL_, 128);

    // 3) offsets + attn logits GEMM
    gemm128_abt<<<dim3((NROWS_ + 127) / 128, 3), 256>>>(query, p_wcat, p_bcat, p_offatt, NROWS_, NCAT_);

    // 4) softmax over 16 per (row, head)
    softmax16_kernel<<<(NROWS_ * NH_ + 255) / 256, 256>>>();

    // 5) bilinear gather + weighted sum
    gather_kernel<<<NROWS_ * NH_ / 4, 128>>>(NEWV, refp);

    // 6) output projection -> new_query
    gemm128_abt<<<dim3((NROWS_ + 127) / 128, 1), 256>>>(p_samp, W_out, b_out, NEWQ, NROWS_, 128);
}

// round 4
// speedup vs baseline: 1.4442x; 1.4442x over previous
#include <cuda_runtime.h>
#include <cuda_bf16.h>
#include <math.h>
#include <stdint.h>

// ---------------- problem constants (fixed by dataset) ----------------
#define B_     8
#define T2_    27
#define T3_    9
#define P_     17
#define C_     128
#define BT2_   216
#define LQ_    153
#define LV_    4080
#define NH_    8
#define NL_    4
#define NP_    4
#define DH_    16
#define NROWS_ (BT2_*LQ_)     // 33048
#define MVAL_  (BT2_*LV_)     // 881280
#define NEWQ_SIZE_ ((size_t)NROWS_*C_)
#define NOFF_  256
#define NCAT_  384

// ---------------- scratch ----------------
__device__ float g_offatt[(size_t)NROWS_ * NCAT_];
__device__ float g_samp[(size_t)NROWS_ * C_];
__device__ float g_wcat[NCAT_ * C_];
__device__ float g_bcat[NCAT_];
// W_val bf16 hi/lo images in the XOR-swizzled [n][k] layout used by vproj smem
__device__ uint32_t g_wb_hi[8192];   // 32KB (128 rows x 256B)
__device__ uint32_t g_wb_lo[8192];   // 32KB

__device__ __forceinline__ uint32_t smem_u32(const void* p) {
    uint32_t a;
    asm("{ .reg .u64 t; cvta.to.shared.u64 t, %1; cvt.u32.u64 %0, t; }" : "=r"(a) : "l"(p));
    return a;
}

// swizzled byte offset within a row: c = byte col (0..255), rm = row & 7
__device__ __host__ __forceinline__ uint32_t swz(uint32_t c, uint32_t rm) {
    return (c & 15u) | ((((c >> 4) ^ rm) & 15u) << 4);
}

// ---------------- prep: convert W_val into hi/lo swizzled images ----------------
__global__ void prep_wval(const float* __restrict__ W) {
    unsigned short* hi = (unsigned short*)g_wb_hi;
    unsigned short* lo = (unsigned short*)g_wb_lo;
    for (int i = threadIdx.x; i < 16384; i += 256) {
        int n = i >> 7, k = i & 127;
        float w = W[i];
        __nv_bfloat16 h = __float2bfloat16_rn(w);
        float wl = w - __bfloat162float(h);
        __nv_bfloat16 l = __float2bfloat16_rn(wl);
        uint32_t byte = (uint32_t)n * 256u + swz((uint32_t)k * 2u, (uint32_t)(n & 7));
        hi[byte >> 1] = __bfloat16_as_ushort(h);
        lo[byte >> 1] = __bfloat16_as_ushort(l);
    }
}

// ---------------- ldmatrix / mma helpers ----------------
#define LDSM4(r0, r1, r2, r3, addr) \
    asm volatile("ldmatrix.sync.aligned.m8n8.x4.shared.b16 {%0,%1,%2,%3}, [%4];" \
                 : "=r"(r0), "=r"(r1), "=r"(r2), "=r"(r3) : "r"(addr))

#define MMA16816(c, a, b0, b1) \
    asm volatile("mma.sync.aligned.m16n8k16.row.col.f32.bf16.bf16.f32 " \
                 "{%0,%1,%2,%3},{%4,%5,%6,%7},{%8,%9},{%0,%1,%2,%3};" \
                 : "+f"((c)[0]), "+f"((c)[1]), "+f"((c)[2]), "+f"((c)[3]) \
                 : "r"((a)[0]), "r"((a)[1]), "r"((a)[2]), "r"((a)[3]), "r"(b0), "r"(b1))

// ---------------- vproj via HMMA bf16 3-term split ----------------
// CTA: 128 threads (4 warps), tile 64(M) x 128(N), K = 128.
// smem: A_hi 16KB | A_lo 16KB | B_hi 32KB | B_lo 32KB = 96KB
#define VPM 64
#define VP_SMEM 98304
#define AHI_OFF 0
#define ALO_OFF 16384
#define BHI_OFF 32768
#define BLO_OFF 65536

__global__ __launch_bounds__(128, 2)
void vproj_mma_kernel(const float* __restrict__ A, const float* __restrict__ bias,
                      float* __restrict__ Out)
{
    extern __shared__ char sm[];
    const uint32_t sbase = smem_u32(sm);
    const int tid = threadIdx.x;
    const int wid = tid >> 5;
    const int lane = tid & 31;
    const int bm = blockIdx.x * VPM;

    // copy pre-swizzled W images into smem (2048 float4 each)
    {
        const float4* shi = (const float4*)g_wb_hi;
        const float4* slo = (const float4*)g_wb_lo;
        float4* dhi = (float4*)(sm + BHI_OFF);
        float4* dlo = (float4*)(sm + BLO_OFF);
#pragma unroll
        for (int i = 0; i < 16; i++) {
            dhi[tid + i * 128] = shi[tid + i * 128];
            dlo[tid + i * 128] = slo[tid + i * 128];
        }
    }

    // convert this CTA's 64x128 A rows into hi/lo bf16 swizzled tiles
    {
        int row = tid >> 1;
        int half = tid & 1;
        const float4* src = (const float4*)(A + (size_t)(bm + row) * 128 + half * 64);
        char* phi = sm + AHI_OFF + row * 256;
        char* plo = sm + ALO_OFF + row * 256;
        uint32_t rm = (uint32_t)(row & 7);
#pragma unroll
        for (int j4 = 0; j4 < 16; j4++) {
            float4 v = src[j4];
            uint32_t c0 = (uint32_t)(half * 128 + j4 * 8);
            uint32_t s0 = swz(c0, rm);
            uint32_t s1 = s0 + 4;          // same 16B chunk
            uint32_t h0, h1, l0, l1;
            asm("cvt.rn.bf16x2.f32 %0, %1, %2;" : "=r"(h0) : "f"(v.y), "f"(v.x));
            asm("cvt.rn.bf16x2.f32 %0, %1, %2;" : "=r"(h1) : "f"(v.w), "f"(v.z));
            float ah0 = __uint_as_float(h0 << 16);
            float ah1 = __uint_as_float(h0 & 0xffff0000u);
            float ah2 = __uint_as_float(h1 << 16);
            float ah3 = __uint_as_float(h1 & 0xffff0000u);
            asm("cvt.rn.bf16x2.f32 %0, %1, %2;" : "=r"(l0) : "f"(v.y - ah1), "f"(v.x - ah0));
            asm("cvt.rn.bf16x2.f32 %0, %1, %2;" : "=r"(l1) : "f"(v.w - ah3), "f"(v.z - ah2));
            *(uint32_t*)(phi + s0) = h0;
            *(uint32_t*)(phi + s1) = h1;
            *(uint32_t*)(plo + s0) = l0;
            *(uint32_t*)(plo + s1) = l1;
        }
    }

    __syncthreads();

    // fragment addressing
    const int sel = lane >> 3;            // 0..3
    const int li  = lane & 7;             // row within 8x8 matrix; also row&7
    const int rA = wid * 16;
    const int arow = rA + li + (sel & 1) * 8;
    const int achunkbit = sel >> 1;       // k-low/high half
    const uint32_t aHiBase = sbase + AHI_OFF + (uint32_t)arow * 256u;
    const uint32_t aLoBase = sbase + ALO_OFF + (uint32_t)arow * 256u;

    const int bchunkbit = sel & 1;
    const int bro = (sel >> 1) * 8 + li;  // row within 16-row n-group
    uint32_t bHiBase[8], bLoBase[8];
#pragma unroll
    for (int g = 0; g < 8; g++) {
        uint32_t nrow = (uint32_t)(g * 16 + bro);
        bHiBase[g] = sbase + BHI_OFF + nrow * 256u;
        bLoBase[g] = sbase + BLO_OFF + nrow * 256u;
    }

    float c[16][4];
#pragma unroll
    for (int t = 0; t < 16; t++)
#pragma unroll
        for (int j = 0; j < 4; j++) c[t][j] = 0.f;

#pragma unroll
    for (int kk = 0; kk < 8; kk++) {
        uint32_t offA = (uint32_t)(((kk * 2 + achunkbit) ^ li) << 4);
        uint32_t offB = (uint32_t)(((kk * 2 + bchunkbit) ^ li) << 4);

        uint32_t ah[4], al[4];
        LDSM4(ah[0], ah[1], ah[2], ah[3], aHiBase + offA);
        LDSM4(al[0], al[1], al[2], al[3], aLoBase + offA);

        uint32_t bh[8][4], bl[8][4];
#pragma unroll
        for (int g = 0; g < 8; g++)
            LDSM4(bh[g][0], bh[g][1], bh[g][2], bh[g][3], bHiBase[g] + offB);
#pragma unroll
        for (int g = 0; g < 8; g++)
            LDSM4(bl[g][0], bl[g][1], bl[g][2], bl[g][3], bLoBase[g] + offB);

        // hh
#pragma unroll
        for (int g = 0; g < 8; g++) {
            MMA16816(c[2 * g],     ah, bh[g][0], bh[g][1]);
            MMA16816(c[2 * g + 1], ah, bh[g][2], bh[g][3]);
        }
        // hl
#pragma unroll
        for (int g = 0; g < 8; g++) {
            MMA16816(c[2 * g],     ah, bl[g][0], bl[g][1]);
            MMA16816(c[2 * g + 1], ah, bl[g][2], bl[g][3]);
        }
        // lh
#pragma unroll
        for (int g = 0; g < 8; g++) {
            MMA16816(c[2 * g],     al, bh[g][0], bh[g][1]);
            MMA16816(c[2 * g + 1], al, bh[g][2], bh[g][3]);
        }
    }

    // epilogue: bias + direct global stores (float2 per acc pair)
    {
        int m0 = bm + rA + (lane >> 2);
        int ncol = 2 * (lane & 3);
#pragma unroll
        for (int t = 0; t < 16; t++) {
            int n = t * 8 + ncol;
            float2 bb = __ldg((const float2*)(bias + n));
            float2 lo2 = make_float2(c[t][0] + bb.x, c[t][1] + bb.y);
            float2 hi2 = make_float2(c[t][2] + bb.x, c[t][3] + bb.y);
            *(float2*)(Out + (size_t)m0 * 128 + n) = lo2;
            *(float2*)(Out + (size_t)(m0 + 8) * 128 + n) = hi2;
        }
    }
}

// ---------------- f32x2 packed-FMA helpers (small GEMMs) ----------------
__device__ __forceinline__ unsigned long long pack2(float x, float y) {
    unsigned long long r;
    asm("mov.b64 %0, {%1, %2};" : "=l"(r) : "f"(x), "f"(y));
    return r;
}
__device__ __forceinline__ unsigned long long dup2(float x) {
    unsigned long long r;
    asm("mov.b64 %0, {%1, %1};" : "=l"(r) : "f"(x));
    return r;
}
__device__ __forceinline__ void ffma2(unsigned long long& d, unsigned long long a, unsigned long long b) {
    asm("fma.rn.f32x2 %0, %1, %2, %0;" : "+l"(d) : "l"(a), "l"(b));
}
__device__ __forceinline__ float2 unpack2(unsigned long long v) {
    float2 f;
    asm("mov.b64 {%0, %1}, %2;" : "=f"(f.x), "=f"(f.y) : "l"(v));
    return f;
}

// ---------------- generic fp32 GEMM (small launches) ----------------
#define KC_ 32
__global__ __launch_bounds__(256) void gemm128_abt(
    const float* __restrict__ A, const float* __restrict__ W,
    const float* __restrict__ bias, float* __restrict__ Out,
    int M, int N)
{
    __shared__ float As[KC_][132];
    __shared__ float Bs[KC_][132];

    const int bm = blockIdx.x * 128;
    const int bn = blockIdx.y * 128;
    const int tid = threadIdx.x;
    const int tx = tid & 15;
    const int ty = tid >> 4;

    unsigned long long acc[8][4];
#pragma unroll
    for (int i = 0; i < 8; i++)
#pragma unroll
        for (int j = 0; j < 4; j++) acc[i][j] = 0ull;

    for (int k0 = 0; k0 < 128; k0 += KC_) {
#pragma unroll
        for (int it = 0; it < 4; it++) {
            int q = it * 256 + tid;
            int row = q >> 3;
            int kq = q & 7;
            int grow = bm + row;
            float4 v = make_float4(0.f, 0.f, 0.f, 0.f);
            if (grow < M)
                v = *(const float4*)(A + (size_t)grow * 128 + k0 + kq * 4);
            As[kq * 4 + 0][row] = v.x;
            As[kq * 4 + 1][row] = v.y;
            As[kq * 4 + 2][row] = v.z;
            As[kq * 4 + 3][row] = v.w;
        }
#pragma unroll
        for (int it = 0; it < 4; it++) {
            int q = it * 256 + tid;
            int row = q >> 3;
            int kq = q & 7;
            float4 v = *(const float4*)(W + (size_t)(bn + row) * 128 + k0 + kq * 4);
            Bs[kq * 4 + 0][row] = v.x;
            Bs[kq * 4 + 1][row] = v.y;
            Bs[kq * 4 + 2][row] = v.z;
            Bs[kq * 4 + 3][row] = v.w;
        }
        __syncthreads();

#pragma unroll
        for (int k = 0; k < KC_; k++) {
            float4 a0 = *(const float4*)&As[k][ty * 8];
            float4 a1 = *(const float4*)&As[k][ty * 8 + 4];
            float4 b0 = *(const float4*)&Bs[k][tx * 8];
            float4 b1 = *(const float4*)&Bs[k][tx * 8 + 4];
            unsigned long long bp0 = pack2(b0.x, b0.y);
            unsigned long long bp1 = pack2(b0.z, b0.w);
            unsigned long long bp2 = pack2(b1.x, b1.y);
            unsigned long long bp3 = pack2(b1.z, b1.w);
            float av[8] = {a0.x, a0.y, a0.z, a0.w, a1.x, a1.y, a1.z, a1.w};
#pragma unroll
            for (int i = 0; i < 8; i++) {
                unsigned long long ad = dup2(av[i]);
                ffma2(acc[i][0], ad, bp0);
                ffma2(acc[i][1], ad, bp1);
                ffma2(acc[i][2], ad, bp2);
                ffma2(acc[i][3], ad, bp3);
            }
        }
        __syncthreads();
    }

    const int gcol = bn + tx * 8;
#pragma unroll
    for (int i = 0; i < 8; i++) {
        int grow = bm + ty * 8 + i;
        if (grow >= M) continue;
        float o[8];
#pragma unroll
        for (int j = 0; j < 4; j++) {
            float2 f = unpack2(acc[i][j]);
            o[j * 2 + 0] = f.x;
            o[j * 2 + 1] = f.y;
        }
#pragma unroll
        for (int j = 0; j < 8; j++) o[j] += bias[gcol + j];
        float* dst = Out + (size_t)grow * N + gcol;
        *(float4*)(dst + 0) = make_float4(o[0], o[1], o[2], o[3]);
        *(float4*)(dst + 4) = make_float4(o[4], o[5], o[6], o[7]);
    }
}

// ---------------- concat W_off|W_attn ----------------
__global__ void concat_weights(const float* __restrict__ Woff, const float* __restrict__ boff,
                               const float* __restrict__ Wattn, const float* __restrict__ battn)
{
    int i = blockIdx.x * 256 + threadIdx.x;
    if (i < NOFF_ * C_)      g_wcat[i] = Woff[i];
    else if (i < NCAT_ * C_) g_wcat[i] = Wattn[i - NOFF_ * C_];
    if (i < NOFF_)           g_bcat[i] = boff[i];
    else if (i < NCAT_)      g_bcat[i] = battn[i - NOFF_];
}

// ---------------- deformable bilinear gather (softmax fused) ----------------
__global__ __launch_bounds__(128) void gather_kernel(
    const float* __restrict__ newv,
    const float* __restrict__ refp)
{
    int g = blockIdx.x * 4 + (threadIdx.x >> 5);
    int r = g >> 3;
    int h = g & 7;
    int lane = threadIdx.x & 31;
    int s = lane >> 1;           // sample 0..15
    int half = lane & 1;
    int l = s >> 2, p = s & 3;
    int b = r / LQ_;

    const int W = 48 >> l;
    const int H = 64 >> l;
    const int start = 4096 - (4096 >> (2 * l));

    int sidx = (h * 4 + l) * 4 + p;
    const float* orow = g_offatt + (size_t)r * NCAT_;
    float offx = orow[sidx * 2 + 0];
    float offy = orow[sidx * 2 + 1];

    // fused softmax over the 16 samples of this (r,h)
    float logit = orow[NOFF_ + h * 16 + s];
    float mx = logit;
#pragma unroll
    for (int m = 2; m <= 16; m <<= 1) mx = fmaxf(mx, __shfl_xor_sync(0xffffffffu, mx, m));
    float e = expf(logit - mx);
    float se = e;
#pragma unroll
    for (int m = 2; m <= 16; m <<= 1) se += __shfl_xor_sync(0xffffffffu, se, m);
    float aw = e / se;

    const float* rp = refp + ((size_t)r * 4 + l) * 2;
    float locx = rp[0] + offx / (float)W;
    float locy = rp[1] + offy / (float)H;
    float px = locx * (float)W - 0.5f;
    float py = locy * (float)H - 0.5f;
    float x0f = floorf(px), y0f = floorf(py);
    float fx = px - x0f, fy = py - y0f;
    int x0 = (int)x0f, y0 = (int)y0f;

    float cw00 = (1.f - fx) * (1.f - fy) * aw;
    float cw10 = fx * (1.f - fy) * aw;
    float cw01 = (1.f - fx) * fy * aw;
    float cw11 = fx * fy * aw;

    const float* base = newv + ((size_t)b * LV_ + start) * C_ + h * DH_ + half * 8;

    float acc[8] = {0.f, 0.f, 0.f, 0.f, 0.f, 0.f, 0.f, 0.f};
    auto corner = [&](int xi, int yi, float cw) {
        if ((unsigned)xi < (unsigned)W && (unsigned)yi < (unsigned)H) {
            const float4* vp = (const float4*)(base + ((size_t)yi * W + xi) * C_);
            float4 v0 = vp[0], v1 = vp[1];
            acc[0] += cw * v0.x; acc[1] += cw * v0.y;
            acc[2] += cw * v0.z; acc[3] += cw * v0.w;
            acc[4] += cw * v1.x; acc[5] += cw * v1.y;
            acc[6] += cw * v1.z; acc[7] += cw * v1.w;
        }
    };
    corner(x0,     y0,     cw00);
    corner(x0 + 1, y0,     cw10);
    corner(x0,     y0 + 1, cw01);
    corner(x0 + 1, y0 + 1, cw11);

#pragma unroll
    for (int m = 2; m <= 16; m <<= 1) {
#pragma unroll
        for (int i = 0; i < 8; i++)
            acc[i] += __shfl_xor_sync(0xffffffffu, acc[i], m);
    }

    if (s == 0) {
        float* dst = g_samp + (size_t)r * C_ + h * DH_ + half * 8;
        *(float4*)(dst + 0) = make_float4(acc[0], acc[1], acc[2], acc[3]);
        *(float4*)(dst + 4) = make_float4(acc[4], acc[5], acc[6], acc[7]);
    }
}

// ---------------- launch ----------------
extern "C" void kernel_launch(void* const* d_in, const int* in_sizes, int n_in,
                              void* d_out, int out_size)
{
    const float* query  = (const float*)d_in[0];
    const float* refp   = (const float*)d_in[1];
    const float* value  = (const float*)d_in[2];
    const float* W_off  = (const float*)d_in[5];
    const float* b_off  = (const float*)d_in[6];
    const float* W_attn = (const float*)d_in[7];
    const float* b_attn = (const float*)d_in[8];
    const float* W_val  = (const float*)d_in[9];
    const float* b_val  = (const float*)d_in[10];
    const float* W_out  = (const float*)d_in[11];
    const float* b_out  = (const float*)d_in[12];

    float* NEWQ = (float*)d_out;
    float* NEWV = NEWQ + NEWQ_SIZE_;

    float *p_offatt, *p_samp, *p_wcat, *p_bcat;
    cudaGetSymbolAddress((void**)&p_offatt, g_offatt);
    cudaGetSymbolAddress((void**)&p_samp,   g_samp);
    cudaGetSymbolAddress((void**)&p_wcat,   g_wcat);
    cudaGetSymbolAddress((void**)&p_bcat,   g_bcat);

    cudaFuncSetAttribute(vproj_mma_kernel, cudaFuncAttributeMaxDynamicSharedMemorySize, VP_SMEM);

    // 1) concat offset/attn weights + prep W_val bf16 images
    concat_weights<<<(NCAT_ * C_ + 255) / 256, 256>>>(W_off, b_off, W_attn, b_attn);
    prep_wval<<<1, 256>>>(W_val);

    // 2) value projection -> new_value (HMMA bf16 3-term split)
    vproj_mma_kernel<<<MVAL_ / VPM, 128, VP_SMEM>>>(value, b_val, NEWV);

    // 3) offsets + attn logits GEMM
    gemm128_abt<<<dim3((NROWS_ + 127) / 128, 3), 256>>>(query, p_wcat, p_bcat, p_offatt, NROWS_, NCAT_);

    // 4) bilinear gather + fused softmax
    gather_kernel<<<NROWS_ * NH_ / 4, 128>>>(NEWV, refp);

    // 5) output projection -> new_query
    gemm128_abt<<<dim3((NROWS_ + 127) / 128, 1), 256>>>(p_samp, W_out, b_out, NEWQ, NROWS_, 128);
}

// round 5
// speedup vs baseline: 1.6650x; 1.1529x over previous
#include <cuda_runtime.h>
#include <cuda_bf16.h>
#include <math.h>
#include <stdint.h>

// ---------------- problem constants (fixed by dataset) ----------------
#define B_     8
#define T2_    27
#define T3_    9
#define P_     17
#define C_     128
#define BT2_   216
#define LQ_    153
#define LV_    4080
#define NH_    8
#define NL_    4
#define NP_    4
#define DH_    16
#define NROWS_ (BT2_*LQ_)     // 33048
#define MVAL_  (BT2_*LV_)     // 881280
#define NEWQ_SIZE_ ((size_t)NROWS_*C_)
#define NOFF_  256
#define NCAT_  384

// ---------------- scratch ----------------
__device__ float g_offatt[(size_t)NROWS_ * NCAT_];
__device__ float g_samp[(size_t)NROWS_ * C_];
__device__ float g_bcat[NCAT_];
// bf16 hi/lo weight images, XOR-swizzled [n][k] layout, 5 chunks of 128x128:
// 0: W_val, 1: W_off[0:128), 2: W_off[128:256), 3: W_attn, 4: W_out
__device__ uint32_t g_wb_hi[5 * 8192];
__device__ uint32_t g_wb_lo[5 * 8192];

__device__ __forceinline__ uint32_t smem_u32(const void* p) {
    uint32_t a;
    asm("{ .reg .u64 t; cvta.to.shared.u64 t, %1; cvt.u32.u64 %0, t; }" : "=r"(a) : "l"(p));
    return a;
}

// swizzled byte offset within a 256B row: c = byte col (0..255), rm = row & 7
__device__ __forceinline__ uint32_t swz(uint32_t c, uint32_t rm) {
    return (c & 15u) | ((((c >> 4) ^ rm) & 15u) << 4);
}

// ---------------- prep: build all 5 weight-chunk hi/lo images ----------------
__global__ void prep_images(const float* __restrict__ W_val,
                            const float* __restrict__ W_off,
                            const float* __restrict__ W_attn,
                            const float* __restrict__ W_out)
{
    const float* srcs[5] = {W_val, W_off, W_off + 16384, W_attn, W_out};
    const float* W = srcs[blockIdx.x];
    unsigned short* hi = (unsigned short*)(g_wb_hi + blockIdx.x * 8192);
    unsigned short* lo = (unsigned short*)(g_wb_lo + blockIdx.x * 8192);
    for (int i = threadIdx.x; i < 16384; i += 256) {
        int n = i >> 7, k = i & 127;
        float w = W[i];
        __nv_bfloat16 h = __float2bfloat16_rn(w);
        float wl = w - __bfloat162float(h);
        __nv_bfloat16 l = __float2bfloat16_rn(wl);
        uint32_t byte = (uint32_t)n * 256u + swz((uint32_t)k * 2u, (uint32_t)(n & 7));
        hi[byte >> 1] = __bfloat16_as_ushort(h);
        lo[byte >> 1] = __bfloat16_as_ushort(l);
    }
}

__global__ void concat_bias(const float* __restrict__ boff, const float* __restrict__ battn) {
    int i = threadIdx.x;
    if (i < NCAT_) g_bcat[i] = (i < NOFF_) ? boff[i] : battn[i - NOFF_];
}

// ---------------- ldmatrix / mma helpers ----------------
#define LDSM4(r0, r1, r2, r3, addr) \
    asm volatile("ldmatrix.sync.aligned.m8n8.x4.shared.b16 {%0,%1,%2,%3}, [%4];" \
                 : "=r"(r0), "=r"(r1), "=r"(r2), "=r"(r3) : "r"(addr))

#define MMA16816(c, a, b0, b1) \
    asm volatile("mma.sync.aligned.m16n8k16.row.col.f32.bf16.bf16.f32 " \
                 "{%0,%1,%2,%3},{%4,%5,%6,%7},{%8,%9},{%0,%1,%2,%3};" \
                 : "+f"((c)[0]), "+f"((c)[1]), "+f"((c)[2]), "+f"((c)[3]) \
                 : "r"((a)[0]), "r"((a)[1]), "r"((a)[2]), "r"((a)[3]), "r"(b0), "r"(b1))

// ---------------- unified HMMA bf16 3-term-split GEMM ----------------
// CTA: 128 threads (4 warps), tile 64(M) x 128(N), K = 128.
// blockIdx.y selects the 128-col weight chunk (image index + output col offset).
// Persistent over M-tiles: tile = blockIdx.x; tile += gridDim.x.
// smem: A_hi 16KB | A_lo 16KB | B_hi 32KB | B_lo 32KB = 96KB
#define VPM 64
#define VP_SMEM 98304
#define AHI_OFF 0
#define ALO_OFF 16384
#define BHI_OFF 32768
#define BLO_OFF 65536

__global__ __launch_bounds__(128, 2)
void hmma_gemm(const float* __restrict__ A,
               const uint32_t* __restrict__ wimg_hi_base,
               const uint32_t* __restrict__ wimg_lo_base,
               const float* __restrict__ bias_base,
               float* __restrict__ Out,
               int M, int ldout, int mtiles)
{
    extern __shared__ char sm[];
    const uint32_t sbase = smem_u32(sm);
    const int tid = threadIdx.x;
    const int wid = tid >> 5;
    const int lane = tid & 31;
    const int colbase = blockIdx.y * 128;
    const float* bias = bias_base + colbase;

    // copy this chunk's pre-swizzled W images into smem (once)
    {
        const float4* shi = (const float4*)(wimg_hi_base + blockIdx.y * 8192);
        const float4* slo = (const float4*)(wimg_lo_base + blockIdx.y * 8192);
        float4* dhi = (float4*)(sm + BHI_OFF);
        float4* dlo = (float4*)(sm + BLO_OFF);
#pragma unroll
        for (int i = 0; i < 16; i++) {
            dhi[tid + i * 128] = shi[tid + i * 128];
            dlo[tid + i * 128] = slo[tid + i * 128];
        }
    }

    // fragment addressing (loop-invariant)
    const int sel = lane >> 3;            // 0..3
    const int li  = lane & 7;
    const int rA = wid * 16;
    const int arow = rA + li + (sel & 1) * 8;
    const int achunkbit = sel >> 1;
    const uint32_t aHiBase = sbase + AHI_OFF + (uint32_t)arow * 256u;
    const uint32_t aLoBase = sbase + ALO_OFF + (uint32_t)arow * 256u;

    const int bchunkbit = sel & 1;
    const int bro = (sel >> 1) * 8 + li;
    uint32_t bHiBase[8], bLoBase[8];
#pragma unroll
    for (int g = 0; g < 8; g++) {
        uint32_t nrow = (uint32_t)(g * 16 + bro);
        bHiBase[g] = sbase + BHI_OFF + nrow * 256u;
        bLoBase[g] = sbase + BLO_OFF + nrow * 256u;
    }

    const int crow = tid >> 1;           // conversion row (0..63)
    const int chalf = tid & 1;
    char* phi = sm + AHI_OFF + crow * 256;
    char* plo = sm + ALO_OFF + crow * 256;
    const uint32_t crm = (uint32_t)(crow & 7);

    for (int tile = blockIdx.x; tile < mtiles; tile += gridDim.x) {
        const int bm = tile * VPM;
        __syncthreads();   // previous iteration's LDSM readers done; W copy done (iter 0)

        // convert this tile's 64x128 A rows into hi/lo bf16 swizzled tiles
        {
            const int grow = bm + crow;
            const bool valid = grow < M;
            const float4* src = (const float4*)(A + (size_t)grow * 128 + chalf * 64);
#pragma unroll
            for (int j4 = 0; j4 < 16; j4++) {
                float4 v = valid ? src[j4] : make_float4(0.f, 0.f, 0.f, 0.f);
                uint32_t c0 = (uint32_t)(chalf * 128 + j4 * 8);
                uint32_t s0 = swz(c0, crm);
                uint32_t s1 = s0 + 4;
                uint32_t h0, h1, l0, l1;
                asm("cvt.rn.bf16x2.f32 %0, %1, %2;" : "=r"(h0) : "f"(v.y), "f"(v.x));
                asm("cvt.rn.bf16x2.f32 %0, %1, %2;" : "=r"(h1) : "f"(v.w), "f"(v.z));
                float ah0 = __uint_as_float(h0 << 16);
                float ah1 = __uint_as_float(h0 & 0xffff0000u);
                float ah2 = __uint_as_float(h1 << 16);
                float ah3 = __uint_as_float(h1 & 0xffff0000u);
                asm("cvt.rn.bf16x2.f32 %0, %1, %2;" : "=r"(l0) : "f"(v.y - ah1), "f"(v.x - ah0));
                asm("cvt.rn.bf16x2.f32 %0, %1, %2;" : "=r"(l1) : "f"(v.w - ah3), "f"(v.z - ah2));
                *(uint32_t*)(phi + s0) = h0;
                *(uint32_t*)(phi + s1) = h1;
                *(uint32_t*)(plo + s0) = l0;
                *(uint32_t*)(plo + s1) = l1;
            }
        }
        __syncthreads();

        float c[16][4];
#pragma unroll
        for (int t = 0; t < 16; t++)
#pragma unroll
            for (int j = 0; j < 4; j++) c[t][j] = 0.f;

#pragma unroll
        for (int kk = 0; kk < 8; kk++) {
            uint32_t offA = (uint32_t)(((kk * 2 + achunkbit) ^ li) << 4);
            uint32_t offB = (uint32_t)(((kk * 2 + bchunkbit) ^ li) << 4);

            uint32_t ah[4], al[4];
            LDSM4(ah[0], ah[1], ah[2], ah[3], aHiBase + offA);
            LDSM4(al[0], al[1], al[2], al[3], aLoBase + offA);

            uint32_t bh[8][4], bl[8][4];
#pragma unroll
            for (int g = 0; g < 8; g++)
                LDSM4(bh[g][0], bh[g][1], bh[g][2], bh[g][3], bHiBase[g] + offB);
#pragma unroll
            for (int g = 0; g < 8; g++)
                LDSM4(bl[g][0], bl[g][1], bl[g][2], bl[g][3], bLoBase[g] + offB);

#pragma unroll
            for (int g = 0; g < 8; g++) {
                MMA16816(c[2 * g],     ah, bh[g][0], bh[g][1]);
                MMA16816(c[2 * g + 1], ah, bh[g][2], bh[g][3]);
            }
#pragma unroll
            for (int g = 0; g < 8; g++) {
                MMA16816(c[2 * g],     ah, bl[g][0], bl[g][1]);
                MMA16816(c[2 * g + 1], ah, bl[g][2], bl[g][3]);
            }
#pragma unroll
            for (int g = 0; g < 8; g++) {
                MMA16816(c[2 * g],     al, bh[g][0], bh[g][1]);
                MMA16816(c[2 * g + 1], al, bh[g][2], bh[g][3]);
            }
        }

        // epilogue: bias + direct global stores
        {
            const int m0 = bm + rA + (lane >> 2);
            const int ncol = 2 * (lane & 3);
            const bool v0 = m0 < M;
            const bool v1 = (m0 + 8) < M;
            float* o0 = Out + (size_t)m0 * ldout + colbase + ncol;
            float* o1 = Out + (size_t)(m0 + 8) * ldout + colbase + ncol;
#pragma unroll
            for (int t = 0; t < 16; t++) {
                int n = t * 8 + ncol;
                float2 bb = __ldg((const float2*)(bias + n));
                if (v0) *(float2*)(o0 + t * 8) = make_float2(c[t][0] + bb.x, c[t][1] + bb.y);
                if (v1) *(float2*)(o1 + t * 8) = make_float2(c[t][2] + bb.x, c[t][3] + bb.y);
            }
        }
    }
}

// ---------------- deformable bilinear gather (softmax fused) ----------------
__global__ __launch_bounds__(128) void gather_kernel(
    const float* __restrict__ newv,
    const float* __restrict__ refp)
{
    int g = blockIdx.x * 4 + (threadIdx.x >> 5);
    int r = g >> 3;
    int h = g & 7;
    int lane = threadIdx.x & 31;
    int s = lane >> 1;           // sample 0..15
    int half = lane & 1;
    int l = s >> 2, p = s & 3;
    int b = r / LQ_;

    const int W = 48 >> l;
    const int H = 64 >> l;
    const int start = 4096 - (4096 >> (2 * l));

    int sidx = (h * 4 + l) * 4 + p;
    const float* orow = g_offatt + (size_t)r * NCAT_;
    float offx = orow[sidx * 2 + 0];
    float offy = orow[sidx * 2 + 1];

    // fused softmax over the 16 samples of this (r,h)
    float logit = orow[NOFF_ + h * 16 + s];
    float mx = logit;
#pragma unroll
    for (int m = 2; m <= 16; m <<= 1) mx = fmaxf(mx, __shfl_xor_sync(0xffffffffu, mx, m));
    float e = expf(logit - mx);
    float se = e;
#pragma unroll
    for (int m = 2; m <= 16; m <<= 1) se += __shfl_xor_sync(0xffffffffu, se, m);
    float aw = e / se;

    const float* rp = refp + ((size_t)r * 4 + l) * 2;
    float locx = rp[0] + offx / (float)W;
    float locy = rp[1] + offy / (float)H;
    float px = locx * (float)W - 0.5f;
    float py = locy * (float)H - 0.5f;
    float x0f = floorf(px), y0f = floorf(py);
    float fx = px - x0f, fy = py - y0f;
    int x0 = (int)x0f, y0 = (int)y0f;

    float cw00 = (1.f - fx) * (1.f - fy) * aw;
    float cw10 = fx * (1.f - fy) * aw;
    float cw01 = (1.f - fx) * fy * aw;
    float cw11 = fx * fy * aw;

    const float* base = newv + ((size_t)b * LV_ + start) * C_ + h * DH_ + half * 8;

    float acc[8] = {0.f, 0.f, 0.f, 0.f, 0.f, 0.f, 0.f, 0.f};
    auto corner = [&](int xi, int yi, float cw) {
        if ((unsigned)xi < (unsigned)W && (unsigned)yi < (unsigned)H) {
            const float4* vp = (const float4*)(base + ((size_t)yi * W + xi) * C_);
            float4 v0 = vp[0], v1 = vp[1];
            acc[0] += cw * v0.x; acc[1] += cw * v0.y;
            acc[2] += cw * v0.z; acc[3] += cw * v0.w;
            acc[4] += cw * v1.x; acc[5] += cw * v1.y;
            acc[6] += cw * v1.z; acc[7] += cw * v1.w;
        }
    };
    corner(x0,     y0,     cw00);
    corner(x0 + 1, y0,     cw10);
    corner(x0,     y0 + 1, cw01);
    corner(x0 + 1, y0 + 1, cw11);

#pragma unroll
    for (int m = 2; m <= 16; m <<= 1) {
#pragma unroll
        for (int i = 0; i < 8; i++)
            acc[i] += __shfl_xor_sync(0xffffffffu, acc[i], m);
    }

    if (s == 0) {
        float* dst = g_samp + (size_t)r * C_ + h * DH_ + half * 8;
        *(float4*)(dst + 0) = make_float4(acc[0], acc[1], acc[2], acc[3]);
        *(float4*)(dst + 4) = make_float4(acc[4], acc[5], acc[6], acc[7]);
    }
}

// ---------------- launch ----------------
extern "C" void kernel_launch(void* const* d_in, const int* in_sizes, int n_in,
                              void* d_out, int out_size)
{
    const float* query  = (const float*)d_in[0];
    const float* refp   = (const float*)d_in[1];
    const float* value  = (const float*)d_in[2];
    const float* W_off  = (const float*)d_in[5];
    const float* b_off  = (const float*)d_in[6];
    const float* W_attn = (const float*)d_in[7];
    const float* b_attn = (const float*)d_in[8];
    const float* W_val  = (const float*)d_in[9];
    const float* b_val  = (const float*)d_in[10];
    const float* W_out  = (const float*)d_in[11];
    const float* b_out  = (const float*)d_in[12];

    float* NEWQ = (float*)d_out;
    float* NEWV = NEWQ + NEWQ_SIZE_;

    float *p_offatt, *p_samp, *p_bcat;
    uint32_t *p_wb_hi, *p_wb_lo;
    cudaGetSymbolAddress((void**)&p_offatt, g_offatt);
    cudaGetSymbolAddress((void**)&p_samp,   g_samp);
    cudaGetSymbolAddress((void**)&p_bcat,   g_bcat);
    cudaGetSymbolAddress((void**)&p_wb_hi,  g_wb_hi);
    cudaGetSymbolAddress((void**)&p_wb_lo,  g_wb_lo);

    cudaFuncSetAttribute(hmma_gemm, cudaFuncAttributeMaxDynamicSharedMemorySize, VP_SMEM);

    // 1) prep weight images + bias concat
    prep_images<<<5, 256>>>(W_val, W_off, W_attn, W_out);
    concat_bias<<<1, NCAT_>>>(b_off, b_attn);

    // 2) value projection -> new_value (persistent: 2 CTAs x 148 SMs)
    hmma_gemm<<<dim3(296, 1), 128, VP_SMEM>>>(
        value, p_wb_hi, p_wb_lo, b_val, NEWV, MVAL_, 128, MVAL_ / VPM);

    // 3) offsets + attn logits (3 weight chunks: indices 1..3)
    {
        int mtiles = (NROWS_ + VPM - 1) / VPM;   // 517
        hmma_gemm<<<dim3(mtiles, 3), 128, VP_SMEM>>>(
            query, p_wb_hi + 8192, p_wb_lo + 8192, p_bcat, p_offatt, NROWS_, NCAT_, mtiles);
    }

    // 4) bilinear gather + fused softmax
    gather_kernel<<<NROWS_ * NH_ / 4, 128>>>(NEWV, refp);

    // 5) output projection -> new_query (chunk 4)
    {
        int mtiles = (NROWS_ + VPM - 1) / VPM;
        hmma_gemm<<<dim3(mtiles, 1), 128, VP_SMEM>>>(
            p_samp, p_wb_hi + 4 * 8192, p_wb_lo + 4 * 8192, b_out, NEWQ, NROWS_, 128, mtiles);
    }
}

// round 6
// speedup vs baseline: 1.7711x; 1.0637x over previous
#include <cuda_runtime.h>
#include <cuda_bf16.h>
#include <math.h>
#include <stdint.h>

// ---------------- problem constants (fixed by dataset) ----------------
#define B_     8
#define T2_    27
#define T3_    9
#define P_     17
#define C_     128
#define BT2_   216
#define LQ_    153
#define LV_    4080
#define NH_    8
#define NL_    4
#define NP_    4
#define DH_    16
#define NROWS_ (BT2_*LQ_)     // 33048
#define MVAL_  (BT2_*LV_)     // 881280
#define NEWQ_SIZE_ ((size_t)NROWS_*C_)
#define NOFF_  256
#define NCAT_  384

// ---------------- scratch ----------------
__device__ float g_offatt[(size_t)NROWS_ * NCAT_];
__device__ float g_samp[(size_t)NROWS_ * C_];
__device__ float g_bcat[NCAT_];
// bf16 hi/lo weight images, XOR-swizzled [n][k] layout, 5 chunks of 128x128:
// 0: W_val, 1: W_off[0:128), 2: W_off[128:256), 3: W_attn, 4: W_out
__device__ uint32_t g_wb_hi[5 * 8192];
__device__ uint32_t g_wb_lo[5 * 8192];

__device__ __forceinline__ uint32_t smem_u32(const void* p) {
    uint32_t a;
    asm("{ .reg .u64 t; cvta.to.shared.u64 t, %1; cvt.u32.u64 %0, t; }" : "=r"(a) : "l"(p));
    return a;
}

// swizzled byte offset within a 256B row: c = byte col (0..255), rm = row & 7
__device__ __forceinline__ uint32_t swz(uint32_t c, uint32_t rm) {
    return (c & 15u) | ((((c >> 4) ^ rm) & 15u) << 4);
}

// ---------------- prep: build all 5 weight-chunk hi/lo images ----------------
__global__ void prep_images(const float* __restrict__ W_val,
                            const float* __restrict__ W_off,
                            const float* __restrict__ W_attn,
                            const float* __restrict__ W_out)
{
    const float* srcs[5] = {W_val, W_off, W_off + 16384, W_attn, W_out};
    const float* W = srcs[blockIdx.x];
    unsigned short* hi = (unsigned short*)(g_wb_hi + blockIdx.x * 8192);
    unsigned short* lo = (unsigned short*)(g_wb_lo + blockIdx.x * 8192);
    for (int i = threadIdx.x; i < 16384; i += 256) {
        int n = i >> 7, k = i & 127;
        float w = W[i];
        __nv_bfloat16 h = __float2bfloat16_rn(w);
        float wl = w - __bfloat162float(h);
        __nv_bfloat16 l = __float2bfloat16_rn(wl);
        uint32_t byte = (uint32_t)n * 256u + swz((uint32_t)k * 2u, (uint32_t)(n & 7));
        hi[byte >> 1] = __bfloat16_as_ushort(h);
        lo[byte >> 1] = __bfloat16_as_ushort(l);
    }
}

__global__ void concat_bias(const float* __restrict__ boff, const float* __restrict__ battn) {
    int i = threadIdx.x;
    if (i < NCAT_) g_bcat[i] = (i < NOFF_) ? boff[i] : battn[i - NOFF_];
}

// ---------------- ldmatrix / mma helpers ----------------
#define LDSM4(r0, r1, r2, r3, addr) \
    asm volatile("ldmatrix.sync.aligned.m8n8.x4.shared.b16 {%0,%1,%2,%3}, [%4];" \
                 : "=r"(r0), "=r"(r1), "=r"(r2), "=r"(r3) : "r"(addr))

#define MMA16816(c, a, b0, b1) \
    asm volatile("mma.sync.aligned.m16n8k16.row.col.f32.bf16.bf16.f32 " \
                 "{%0,%1,%2,%3},{%4,%5,%6,%7},{%8,%9},{%0,%1,%2,%3};" \
                 : "+f"((c)[0]), "+f"((c)[1]), "+f"((c)[2]), "+f"((c)[3]) \
                 : "r"((a)[0]), "r"((a)[1]), "r"((a)[2]), "r"((a)[3]), "r"(b0), "r"(b1))

// ---------------- unified HMMA bf16 3-term-split GEMM ----------------
// CTA: 128 threads (4 warps), tile 64(M) x 128(N), K = 128.
// Warp layout 2x2: warp (wm, wn) computes m-range [wm*32, wm*32+32) x
// n-range [wn*64, wn*64+64).  Each B fragment feeds 2 m-sub-bands -> B LDSM
// traffic halved vs 4-warps-along-M.
// blockIdx.y selects the 128-col weight chunk. Persistent over M-tiles.
// smem: A_hi 16KB | A_lo 16KB | B_hi 32KB | B_lo 32KB = 96KB
#define VPM 64
#define VP_SMEM 98304
#define AHI_OFF 0
#define ALO_OFF 16384
#define BHI_OFF 32768
#define BLO_OFF 65536

__global__ __launch_bounds__(128, 2)
void hmma_gemm(const float* __restrict__ A,
               const uint32_t* __restrict__ wimg_hi_base,
               const uint32_t* __restrict__ wimg_lo_base,
               const float* __restrict__ bias_base,
               float* __restrict__ Out,
               int M, int ldout, int mtiles)
{
    extern __shared__ char sm[];
    const uint32_t sbase = smem_u32(sm);
    const int tid = threadIdx.x;
    const int wid = tid >> 5;
    const int lane = tid & 31;
    const int wm = wid & 1;          // m half (32 rows)
    const int wn = wid >> 1;         // n half (64 cols)
    const int colbase = blockIdx.y * 128;
    const float* bias = bias_base + colbase;

    // copy this chunk's pre-swizzled W images into smem (once)
    {
        const float4* shi = (const float4*)(wimg_hi_base + blockIdx.y * 8192);
        const float4* slo = (const float4*)(wimg_lo_base + blockIdx.y * 8192);
        float4* dhi = (float4*)(sm + BHI_OFF);
        float4* dlo = (float4*)(sm + BLO_OFF);
#pragma unroll
        for (int i = 0; i < 16; i++) {
            dhi[tid + i * 128] = shi[tid + i * 128];
            dlo[tid + i * 128] = slo[tid + i * 128];
        }
    }

    // fragment addressing (loop-invariant)
    const int sel = lane >> 3;            // 0..3
    const int li  = lane & 7;
    const int achunkbit = sel >> 1;
    // two m-sub-bands per warp: rows wm*32 + s*16
    uint32_t aHiB[2], aLoB[2];
#pragma unroll
    for (int s = 0; s < 2; s++) {
        int arow = wm * 32 + s * 16 + li + (sel & 1) * 8;
        aHiB[s] = sbase + AHI_OFF + (uint32_t)arow * 256u;
        aLoB[s] = sbase + ALO_OFF + (uint32_t)arow * 256u;
    }

    const int bchunkbit = sel & 1;
    const int bro = (sel >> 1) * 8 + li;
    uint32_t bHiBase[4], bLoBase[4];
#pragma unroll
    for (int g = 0; g < 4; g++) {
        uint32_t nrow = (uint32_t)((wn * 4 + g) * 16 + bro);
        bHiBase[g] = sbase + BHI_OFF + nrow * 256u;
        bLoBase[g] = sbase + BLO_OFF + nrow * 256u;
    }

    const int crow = tid >> 1;           // conversion row (0..63)
    const int chalf = tid & 1;
    char* phi = sm + AHI_OFF + crow * 256;
    char* plo = sm + ALO_OFF + crow * 256;
    const uint32_t crm = (uint32_t)(crow & 7);

    for (int tile = blockIdx.x; tile < mtiles; tile += gridDim.x) {
        const int bm = tile * VPM;
        __syncthreads();   // prior readers done / W copy done (iter 0)

        // convert this tile's 64x128 A rows into hi/lo bf16 swizzled tiles
        {
            const int grow = bm + crow;
            const bool valid = grow < M;
            const float4* src = (const float4*)(A + (size_t)grow * 128 + chalf * 64);
#pragma unroll
            for (int j4 = 0; j4 < 16; j4++) {
                float4 v = valid ? src[j4] : make_float4(0.f, 0.f, 0.f, 0.f);
                uint32_t c0 = (uint32_t)(chalf * 128 + j4 * 8);
                uint32_t s0 = swz(c0, crm);
                uint32_t s1 = s0 + 4;
                uint32_t h0, h1, l0, l1;
                asm("cvt.rn.bf16x2.f32 %0, %1, %2;" : "=r"(h0) : "f"(v.y), "f"(v.x));
                asm("cvt.rn.bf16x2.f32 %0, %1, %2;" : "=r"(h1) : "f"(v.w), "f"(v.z));
                float ah0 = __uint_as_float(h0 << 16);
                float ah1 = __uint_as_float(h0 & 0xffff0000u);
                float ah2 = __uint_as_float(h1 << 16);
                float ah3 = __uint_as_float(h1 & 0xffff0000u);
                asm("cvt.rn.bf16x2.f32 %0, %1, %2;" : "=r"(l0) : "f"(v.y - ah1), "f"(v.x - ah0));
                asm("cvt.rn.bf16x2.f32 %0, %1, %2;" : "=r"(l1) : "f"(v.w - ah3), "f"(v.z - ah2));
                *(uint32_t*)(phi + s0) = h0;
                *(uint32_t*)(phi + s1) = h1;
                *(uint32_t*)(plo + s0) = l0;
                *(uint32_t*)(plo + s1) = l1;
            }
        }
        __syncthreads();

        float c[2][8][4];
#pragma unroll
        for (int s = 0; s < 2; s++)
#pragma unroll
            for (int t = 0; t < 8; t++)
#pragma unroll
                for (int j = 0; j < 4; j++) c[s][t][j] = 0.f;

#pragma unroll
        for (int kk = 0; kk < 8; kk++) {
            uint32_t offA = (uint32_t)(((kk * 2 + achunkbit) ^ li) << 4);
            uint32_t offB = (uint32_t)(((kk * 2 + bchunkbit) ^ li) << 4);

            uint32_t ah[2][4], al[2][4];
#pragma unroll
            for (int s = 0; s < 2; s++) {
                LDSM4(ah[s][0], ah[s][1], ah[s][2], ah[s][3], aHiB[s] + offA);
                LDSM4(al[s][0], al[s][1], al[s][2], al[s][3], aLoB[s] + offA);
            }

#pragma unroll
            for (int g = 0; g < 4; g++) {
                uint32_t bh[4], bl[4];
                LDSM4(bh[0], bh[1], bh[2], bh[3], bHiBase[g] + offB);
                LDSM4(bl[0], bl[1], bl[2], bl[3], bLoBase[g] + offB);
#pragma unroll
                for (int s = 0; s < 2; s++) {
                    MMA16816(c[s][2 * g],     ah[s], bh[0], bh[1]);
                    MMA16816(c[s][2 * g + 1], ah[s], bh[2], bh[3]);
                    MMA16816(c[s][2 * g],     al[s], bh[0], bh[1]);
                    MMA16816(c[s][2 * g + 1], al[s], bh[2], bh[3]);
                    MMA16816(c[s][2 * g],     ah[s], bl[0], bl[1]);
                    MMA16816(c[s][2 * g + 1], ah[s], bl[2], bl[3]);
                }
            }
        }

        // epilogue: bias + direct global stores
        {
            const int ncol = wn * 64 + 2 * (lane & 3);
#pragma unroll
            for (int s = 0; s < 2; s++) {
                const int m0 = bm + wm * 32 + s * 16 + (lane >> 2);
                const bool v0 = m0 < M;
                const bool v1 = (m0 + 8) < M;
                float* o0 = Out + (size_t)m0 * ldout + colbase;
                float* o1 = Out + (size_t)(m0 + 8) * ldout + colbase;
#pragma unroll
                for (int t = 0; t < 8; t++) {
                    int n = ncol + t * 8;
                    float2 bb = __ldg((const float2*)(bias + n));
                    if (v0) *(float2*)(o0 + n) = make_float2(c[s][t][0] + bb.x, c[s][t][1] + bb.y);
                    if (v1) *(float2*)(o1 + n) = make_float2(c[s][t][2] + bb.x, c[s][t][3] + bb.y);
                }
            }
        }
    }
}

// ---------------- deformable bilinear gather (softmax fused) ----------------
__global__ __launch_bounds__(128) void gather_kernel(
    const float* __restrict__ newv,
    const float* __restrict__ refp)
{
    int g = blockIdx.x * 4 + (threadIdx.x >> 5);
    int r = g >> 3;
    int h = g & 7;
    int lane = threadIdx.x & 31;
    int s = lane >> 1;           // sample 0..15
    int half = lane & 1;
    int l = s >> 2, p = s & 3;
    int b = r / LQ_;

    const int W = 48 >> l;
    const int H = 64 >> l;
    const int start = 4096 - (4096 >> (2 * l));

    int sidx = (h * 4 + l) * 4 + p;
    const float* orow = g_offatt + (size_t)r * NCAT_;
    float offx = orow[sidx * 2 + 0];
    float offy = orow[sidx * 2 + 1];

    // fused softmax over the 16 samples of this (r,h)
    float logit = orow[NOFF_ + h * 16 + s];
    float mx = logit;
#pragma unroll
    for (int m = 2; m <= 16; m <<= 1) mx = fmaxf(mx, __shfl_xor_sync(0xffffffffu, mx, m));
    float e = expf(logit - mx);
    float se = e;
#pragma unroll
    for (int m = 2; m <= 16; m <<= 1) se += __shfl_xor_sync(0xffffffffu, se, m);
    float aw = e / se;

    const float* rp = refp + ((size_t)r * 4 + l) * 2;
    float locx = rp[0] + offx / (float)W;
    float locy = rp[1] + offy / (float)H;
    float px = locx * (float)W - 0.5f;
    float py = locy * (float)H - 0.5f;
    float x0f = floorf(px), y0f = floorf(py);
    float fx = px - x0f, fy = py - y0f;
    int x0 = (int)x0f, y0 = (int)y0f;

    float cw00 = (1.f - fx) * (1.f - fy) * aw;
    float cw10 = fx * (1.f - fy) * aw;
    float cw01 = (1.f - fx) * fy * aw;
    float cw11 = fx * fy * aw;

    const float* base = newv + ((size_t)b * LV_ + start) * C_ + h * DH_ + half * 8;

    float acc[8] = {0.f, 0.f, 0.f, 0.f, 0.f, 0.f, 0.f, 0.f};
    auto corner = [&](int xi, int yi, float cw) {
        if ((unsigned)xi < (unsigned)W && (unsigned)yi < (unsigned)H) {
            const float4* vp = (const float4*)(base + ((size_t)yi * W + xi) * C_);
            float4 v0 = vp[0], v1 = vp[1];
            acc[0] += cw * v0.x; acc[1] += cw * v0.y;
            acc[2] += cw * v0.z; acc[3] += cw * v0.w;
            acc[4] += cw * v1.x; acc[5] += cw * v1.y;
            acc[6] += cw * v1.z; acc[7] += cw * v1.w;
        }
    };
    corner(x0,     y0,     cw00);
    corner(x0 + 1, y0,     cw10);
    corner(x0,     y0 + 1, cw01);
    corner(x0 + 1, y0 + 1, cw11);

#pragma unroll
    for (int m = 2; m <= 16; m <<= 1) {
#pragma unroll
        for (int i = 0; i < 8; i++)
            acc[i] += __shfl_xor_sync(0xffffffffu, acc[i], m);
    }

    if (s == 0) {
        float* dst = g_samp + (size_t)r * C_ + h * DH_ + half * 8;
        *(float4*)(dst + 0) = make_float4(acc[0], acc[1], acc[2], acc[3]);
        *(float4*)(dst + 4) = make_float4(acc[4], acc[5], acc[6], acc[7]);
    }
}

// ---------------- launch ----------------
extern "C" void kernel_launch(void* const* d_in, const int* in_sizes, int n_in,
                              void* d_out, int out_size)
{
    const float* query  = (const float*)d_in[0];
    const float* refp   = (const float*)d_in[1];
    const float* value  = (const float*)d_in[2];
    const float* W_off  = (const float*)d_in[5];
    const float* b_off  = (const float*)d_in[6];
    const float* W_attn = (const float*)d_in[7];
    const float* b_attn = (const float*)d_in[8];
    const float* W_val  = (const float*)d_in[9];
    const float* b_val  = (const float*)d_in[10];
    const float* W_out  = (const float*)d_in[11];
    const float* b_out  = (const float*)d_in[12];

    float* NEWQ = (float*)d_out;
    float* NEWV = NEWQ + NEWQ_SIZE_;

    float *p_offatt, *p_samp, *p_bcat;
    uint32_t *p_wb_hi, *p_wb_lo;
    cudaGetSymbolAddress((void**)&p_offatt, g_offatt);
    cudaGetSymbolAddress((void**)&p_samp,   g_samp);
    cudaGetSymbolAddress((void**)&p_bcat,   g_bcat);
    cudaGetSymbolAddress((void**)&p_wb_hi,  g_wb_hi);
    cudaGetSymbolAddress((void**)&p_wb_lo,  g_wb_lo);

    cudaFuncSetAttribute(hmma_gemm, cudaFuncAttributeMaxDynamicSharedMemorySize, VP_SMEM);

    // 1) prep weight images + bias concat
    prep_images<<<5, 256>>>(W_val, W_off, W_attn, W_out);
    concat_bias<<<1, NCAT_>>>(b_off, b_attn);

    // 2) value projection -> new_value (persistent: 2 CTAs x 148 SMs)
    hmma_gemm<<<dim3(296, 1), 128, VP_SMEM>>>(
        value, p_wb_hi, p_wb_lo, b_val, NEWV, MVAL_, 128, MVAL_ / VPM);

    // 3) offsets + attn logits (3 weight chunks: indices 1..3)
    {
        int mtiles = (NROWS_ + VPM - 1) / VPM;   // 517
        hmma_gemm<<<dim3(mtiles, 3), 128, VP_SMEM>>>(
            query, p_wb_hi + 8192, p_wb_lo + 8192, p_bcat, p_offatt, NROWS_, NCAT_, mtiles);
    }

    // 4) bilinear gather + fused softmax
    gather_kernel<<<NROWS_ * NH_ / 4, 128>>>(NEWV, refp);

    // 5) output projection -> new_query (chunk 4)
    {
        int mtiles = (NROWS_ + VPM - 1) / VPM;
        hmma_gemm<<<dim3(mtiles, 1), 128, VP_SMEM>>>(
            p_samp, p_wb_hi + 4 * 8192, p_wb_lo + 4 * 8192, b_out, NEWQ, NROWS_, 128, mtiles);
    }
}